// round 12
// baseline (speedup 1.0000x reference)
#include <cuda_runtime.h>
#include <cuda_bf16.h>
#include <cstdint>

#define PITCH 1026
// g_pos[n][i][t + s(i)], s(i)=(i+1)&1 -> flash shifted reads are 8B aligned
__device__ float g_pos[(size_t)64 * 1024 * PITCH];
// preconverted operands
__device__ __nv_bfloat16 g_kh[(size_t)64 * 1024 * 64];
__device__ __nv_bfloat16 g_kl[(size_t)64 * 1024 * 64];
__device__ __nv_bfloat16 g_vth[(size_t)64 * 64 * 1024];   // V^T: [n][d][j]
__device__ __nv_bfloat16 g_vtl[(size_t)64 * 64 * 1024];
__device__ __nv_bfloat16 g_rh[(size_t)16 * 1024 * 64];    // R hi: [h][t][d]
__device__ __nv_bfloat16 g_rl[(size_t)16 * 1024 * 64];

// ------------------------------ helpers -----------------------------------
__device__ __forceinline__ uint32_t smem_u32(const void* p) {
    uint32_t a;
    asm("{ .reg .u64 t; cvta.to.shared.u64 t, %1; cvt.u32.u64 %0, t; }" : "=r"(a) : "l"(p));
    return a;
}
__device__ __forceinline__ void ldsm4(uint32_t* r, uint32_t a) {
    asm volatile("ldmatrix.sync.aligned.m8n8.x4.shared.b16 {%0,%1,%2,%3}, [%4];"
        : "=r"(r[0]), "=r"(r[1]), "=r"(r[2]), "=r"(r[3]) : "r"(a));
}
__device__ __forceinline__ void mma16816(float* c, const uint32_t* a, const uint32_t* b) {
    asm volatile("mma.sync.aligned.m16n8k16.row.col.f32.bf16.bf16.f32 "
        "{%0,%1,%2,%3}, {%4,%5,%6,%7}, {%8,%9}, {%0,%1,%2,%3};"
        : "+f"(c[0]), "+f"(c[1]), "+f"(c[2]), "+f"(c[3])
        : "r"(a[0]), "r"(a[1]), "r"(a[2]), "r"(a[3]), "r"(b[0]), "r"(b[1]));
}
__device__ __forceinline__ void splitpair(float a, float b, uint32_t& hi, uint32_t& lo) {
    __nv_bfloat16 ah = __float2bfloat16_rn(a), bh = __float2bfloat16_rn(b);
    __nv_bfloat16 al = __float2bfloat16_rn(a - __bfloat162float(ah));
    __nv_bfloat16 bl = __float2bfloat16_rn(b - __bfloat162float(bh));
    __nv_bfloat162 h2, l2; h2.x = ah; h2.y = bh; l2.x = al; l2.y = bl;
    hi = *reinterpret_cast<uint32_t*>(&h2); lo = *reinterpret_cast<uint32_t*>(&l2);
}
__device__ __forceinline__ float posval(const float* pb, int i, int j) {
    if (j <= i)     return pb[(size_t)i * PITCH + (1023 + j - i + ((i + 1) & 1))];
    if (j == i + 1) return 0.0f;
    return pb[(size_t)(i + 1) * PITCH + (j - i - 2 + ((i + 2) & 1))];
}
#define CPA16(dst, src) asm volatile("cp.async.cg.shared.global [%0], [%1], 16;" :: "r"(dst), "l"(src))
#define CPA_COMMIT()    asm volatile("cp.async.commit_group;" ::: "memory")

// ---------------------------------------------------------------------------
// Kernel 0a: preconvert K -> (hi,lo) bf16 [n][j][d]; V -> transposed (hi,lo)
// bf16 [n][d][j]. grid (16 jt, 64 n), 256 thr.
// ---------------------------------------------------------------------------
__global__ __launch_bounds__(256)
void prep_kv(const float* __restrict__ k, const float* __restrict__ v)
{
    __shared__ float vs[64 * 65];
    const int tid = threadIdx.x, n = blockIdx.y, jt = blockIdx.x;
    const float* kb = k + (size_t)n * 65536 + jt * 4096;
    const float* vb = v + (size_t)n * 65536 + jt * 4096;

    #pragma unroll
    for (int it = 0; it < 4; ++it) {
        int fi = it * 256 + tid;
        int r = fi >> 4, d = (fi & 15) << 2;
        float4 f = *(const float4*)(kb + r * 64 + d);
        uint32_t h0, l0, h1, l1;
        splitpair(f.x, f.y, h0, l0); splitpair(f.z, f.w, h1, l1);
        size_t o = (((size_t)n * 1024 + jt * 64 + r) << 6) + d;
        *(uint2*)(g_kh + o) = make_uint2(h0, h1);
        *(uint2*)(g_kl + o) = make_uint2(l0, l1);
        float4 g = *(const float4*)(vb + r * 64 + d);
        vs[r * 65 + d + 0] = g.x; vs[r * 65 + d + 1] = g.y;
        vs[r * 65 + d + 2] = g.z; vs[r * 65 + d + 3] = g.w;
    }
    __syncthreads();
    #pragma unroll
    for (int it = 0; it < 4; ++it) {
        int fi = it * 256 + tid;
        int d = fi >> 4, j = (fi & 15) << 2;
        float a0 = vs[(j + 0) * 65 + d], a1 = vs[(j + 1) * 65 + d];
        float a2 = vs[(j + 2) * 65 + d], a3 = vs[(j + 3) * 65 + d];
        uint32_t h0, l0, h1, l1;
        splitpair(a0, a1, h0, l0); splitpair(a2, a3, h1, l1);
        size_t o = (((size_t)n * 64 + d) << 10) + jt * 64 + j;
        *(uint2*)(g_vth + o) = make_uint2(h0, h1);
        *(uint2*)(g_vtl + o) = make_uint2(l0, l1);
    }
}

// ---------------------------------------------------------------------------
// Kernel 0b: preconvert R -> (hi,lo) bf16 [h][t][d], t < 1024. grid (16 tt, 16 h).
// ---------------------------------------------------------------------------
__global__ __launch_bounds__(256)
void prep_r(const float* __restrict__ R)
{
    const int tid = threadIdx.x, h = blockIdx.y, tt = blockIdx.x;
    const float* rb = R + (size_t)h * (2048 * 64) + tt * 4096;
    #pragma unroll
    for (int it = 0; it < 4; ++it) {
        int fi = it * 256 + tid;
        int r = fi >> 4, d = (fi & 15) << 2;
        float4 f = *(const float4*)(rb + r * 64 + d);
        uint32_t h0, l0, h1, l1;
        splitpair(f.x, f.y, h0, l0); splitpair(f.z, f.w, h1, l1);
        size_t o = (((size_t)h * 1024 + tt * 64 + r) << 6) + d;
        *(uint2*)(g_rh + o) = make_uint2(h0, h1);
        *(uint2*)(g_rl + o) = make_uint2(l0, l1);
    }
}

// ---------------------------------------------------------------------------
// Kernel 1: g_pos(shifted) = (q*0.125 + vbias) . R^T  via mma.sync bf16x3.
// v4: BM=64, grid (16 i, 64 n), 256 thr = 8 warps 4(M)x2(N); 3-stage cp.async,
// ONE sync/iter, direct fragment STG epilogue (no smem staging).
// smem 73728 -> up to 3 CTAs/SM.
// ---------------------------------------------------------------------------
#define PQH 0
#define PQL 9216
#define PRB 18432            /* 3 bufs of 18432 (hi 0, lo +9216) */
#define POS_SMEM 73728

__global__ __launch_bounds__(256)
void pos_mma(const float* __restrict__ q, const float* __restrict__ vbias)
{
    extern __shared__ char cb[];
    uint32_t sb = smem_u32(cb);

    const int tid = threadIdx.x, lane = tid & 31, wid = tid >> 5;
    const int wm = wid >> 1, wn = wid & 1;       // 4 M-groups x 2 N-groups
    const int n = blockIdx.y, h = n & 15;
    const int i0 = blockIdx.x << 6;

    // stage Qv = q*0.125 + vbias (hi/lo) once: 64 rows
    const float* qb = q + (size_t)n * 65536 + (size_t)i0 * 64;
    #pragma unroll
    for (int it = 0; it < 4; ++it) {
        int fi = it * 256 + tid;
        int r = fi >> 4, d = (fi & 15) << 2;
        float4 f = *(const float4*)(qb + r * 64 + d);
        float4 bs = *(const float4*)(vbias + h * 64 + d);
        f.x = f.x * 0.125f + bs.x; f.y = f.y * 0.125f + bs.y;
        f.z = f.z * 0.125f + bs.z; f.w = f.w * 0.125f + bs.w;
        uint2 H, L;
        splitpair(f.x, f.y, H.x, L.x); splitpair(f.z, f.w, H.y, L.y);
        *(uint2*)(cb + PQH + r * 144 + d * 2) = H;
        *(uint2*)(cb + PQL + r * 144 + d * 2) = L;
    }

    const char* ghb = (const char*)(g_rh + ((size_t)h << 16));
    const char* glb = (const char*)(g_rl + ((size_t)h << 16));

    #define ISSUE_R(kt, base) do {                                             \
        const char* _gh = ghb + ((size_t)(kt) << 13);                          \
        const char* _gl = glb + ((size_t)(kt) << 13);                          \
        _Pragma("unroll")                                                      \
        for (int c = tid; c < 512; c += 256) {                                 \
            uint32_t so = (uint32_t)((c >> 3) * 144 + ((c & 7) << 4));         \
            uint32_t go = (uint32_t)(((c >> 3) << 7) + ((c & 7) << 4));        \
            CPA16(sb + (base) + so, _gh + go);                                 \
            CPA16(sb + (base) + 9216 + so, _gl + go);                         \
        }                                                                      \
        CPA_COMMIT();                                                          \
    } while (0)

    ISSUE_R(0, PRB);

    // precomputed shifted output row pointers (this thread's two rows)
    float* gpn = g_pos + (size_t)n * (1024 * PITCH);
    const int g = lane >> 2, t4 = lane & 3;
    const int ia = i0 + wm * 16 + g, ib = ia + 8;
    float* gpa = gpn + (size_t)ia * PITCH + ((ia + 1) & 1);
    float* gpb = gpn + (size_t)ib * PITCH + ((ib + 1) & 1);
    const int cbase = wn * 32 + (t4 << 1);

    for (int kt = 0; kt < 16; ++kt) {
        const uint32_t rB = PRB + (kt % 3) * 18432;
        if (kt < 15) {
            ISSUE_R(kt + 1, PRB + ((kt + 1) % 3) * 18432);
            asm volatile("cp.async.wait_group 1;" ::: "memory");
        } else {
            asm volatile("cp.async.wait_group 0;" ::: "memory");
        }
        __syncthreads();   // buf kt ready; all MMA reads of buf (kt-1) done

        // ---- C = Qv . R^T (bf16x3); warp tile 16(i) x 32(t) ----
        float sC[4][4] = {};
        #pragma unroll
        for (int ks = 0; ks < 4; ++ks) {
            uint32_t qh[4], ql[4], rh[2][4], rl[2][4];
            uint32_t qa = (wm * 16 + (lane & 15)) * 144 +
                          (ks * 16 + ((lane >> 4) << 3)) * 2;
            ldsm4(qh, sb + PQH + qa);
            ldsm4(ql, sb + PQL + qa);
            #pragma unroll
            for (int p = 0; p < 2; ++p) {
                uint32_t ao = (wn * 32 + p * 16 + (lane & 7) + ((lane >> 4) << 3)) * 144 +
                              (ks * 16 + (((lane >> 3) & 1) << 3)) * 2;
                ldsm4(rh[p], sb + rB + ao);
                ldsm4(rl[p], sb + rB + 9216 + ao);
            }
            #pragma unroll
            for (int p = 0; p < 2; ++p) {
                mma16816(sC[2*p],     qh, rh[p]);
                mma16816(sC[2*p],     qh, rl[p]);
                mma16816(sC[2*p],     ql, rh[p]);
                mma16816(sC[2*p + 1], qh, rh[p] + 2);
                mma16816(sC[2*p + 1], qh, rl[p] + 2);
                mma16816(sC[2*p + 1], ql, rh[p] + 2);
            }
        }

        // ---- direct shifted store of fragments (4B stores, rows covered) ----
        const int t0 = kt << 6;
        #pragma unroll
        for (int nt = 0; nt < 4; ++nt) {
            const int c = t0 + cbase + nt * 8;
            gpa[c]     = sC[nt][0];
            gpa[c + 1] = sC[nt][1];
            gpb[c]     = sC[nt][2];
            gpb[c + 1] = sC[nt][3];
        }
    }
    #undef ISSUE_R
}

// ---------------------------------------------------------------------------
// Kernel 2: flash attention, bf16x3, P in registers, 3-stage cp.async pipeline,
// ONE __syncthreads per iteration, hoisted pos row pointers.
// BM=128(i), BN=64(j), 16 iters. 512 thr = 16 warps as 8(M)x2(N).
// grid (8 i-tiles, 64 n).
// ---------------------------------------------------------------------------
#define QUH_O 0
#define QUL_O 18432
#define ST0_O 36864          /* stage: KH 0 | KL 9216 | VTH 18432 | VTL 27648 */
#define ST_SZ 36864
#define LS_O  (ST0_O + 3 * ST_SZ)      /* 147456 */
#define OB_O  (ST0_O + ST_SZ)          /* buf1 overlay (last iter reads buf0) */
#define FLASH_SMEM (LS_O + 1024)       /* 148480 */

__global__ __launch_bounds__(512)
void flash_mma(const float* __restrict__ q, const float* __restrict__ ubias,
               float* __restrict__ out)
{
    extern __shared__ char cb[];
    uint32_t sb = smem_u32(cb);

    const int tid = threadIdx.x, lane = tid & 31, wid = tid >> 5;
    const int wm = wid >> 1, wn = wid & 1;       // 8 M-rows x 2 N-cols
    const int n = blockIdx.y, h = n & 15;
    const int i0 = blockIdx.x << 7;

    // stage Qu = q*0.125 + u_bias (hi/lo)
    const float* qb = q + (size_t)n * 65536 + (size_t)i0 * 64;
    #pragma unroll
    for (int it = 0; it < 4; ++it) {
        int fi = it * 512 + tid;
        int r = fi >> 4, d = (fi & 15) << 2;
        float4 f = *(const float4*)(qb + r * 64 + d);
        float4 bs = *(const float4*)(ubias + h * 64 + d);
        f.x = f.x * 0.125f + bs.x; f.y = f.y * 0.125f + bs.y;
        f.z = f.z * 0.125f + bs.z; f.w = f.w * 0.125f + bs.w;
        uint2 H, L;
        splitpair(f.x, f.y, H.x, L.x); splitpair(f.z, f.w, H.y, L.y);
        *(uint2*)(cb + QUH_O + r * 144 + d * 2) = H;
        *(uint2*)(cb + QUL_O + r * 144 + d * 2) = L;
    }

    float oC[8][4] = {};
    float ls[2] = {};
    const float* pb = g_pos + (size_t)n * (1024 * PITCH);

    const int g = lane >> 2, t4 = lane & 3;
    const int i1 = i0 + wm * 16 + g;
    const int i2 = i1 + 8;

    // hoisted shifted pos row pointers (loop-invariant)
    const float* rp0a = pb + (size_t)i1 * PITCH + (1023 - i1 + ((i1 + 1) & 1));
    const float* rp1a = pb + (size_t)(i1 + 1) * PITCH + (((i1 + 2) & 1) - i1 - 2);
    const float* rp0b = pb + (size_t)i2 * PITCH + (1023 - i2 + ((i2 + 1) & 1));
    const float* rp1b = pb + (size_t)(i2 + 1) * PITCH + (((i2 + 2) & 1) - i2 - 2);

    const int cr = tid >> 3;
    const int coff = (tid & 7) << 4;
    const char* khb = (const char*)(g_kh + (((size_t)n * 1024 + cr) << 6)) + coff;
    const char* klb = (const char*)(g_kl + (((size_t)n * 1024 + cr) << 6)) + coff;
    const char* vhb = (const char*)(g_vth + (((size_t)n * 64 + cr) << 10)) + coff;
    const char* vlb = (const char*)(g_vtl + (((size_t)n * 64 + cr) << 10)) + coff;
    const uint32_t sdst = sb + cr * 144 + coff;

    #define ISSUE(kt, st) do {                                              \
        CPA16(sdst + (st) + 0,     khb + ((size_t)(kt) << 13));             \
        CPA16(sdst + (st) + 9216,  klb + ((size_t)(kt) << 13));             \
        CPA16(sdst + (st) + 18432, vhb + ((size_t)(kt) << 7));              \
        CPA16(sdst + (st) + 27648, vlb + ((size_t)(kt) << 7));              \
        CPA_COMMIT();                                                       \
    } while (0)

    ISSUE(0, ST0_O);

    for (int kt = 0; kt < 16; ++kt) {
        const uint32_t st = ST0_O + (kt % 3) * ST_SZ;

        // ---- pos prefetch with hoisted pointers (overlaps cp.async) ----
        float pr[4][4];
        const int jb = (kt << 6) + wn * 32 + (t4 << 1);
        #pragma unroll
        for (int nt = 0; nt < 4; ++nt) {
            const int j = jb + nt * 8;
            float2 pp;
            if (j + 1 <= i1)      pp = *(const float2*)(rp0a + j);
            else if (j >= i1 + 2) pp = *(const float2*)(rp1a + j);
            else { pp.x = posval(pb, i1, j); pp.y = posval(pb, i1, j + 1); }
            pr[nt][0] = pp.x; pr[nt][1] = pp.y;
            if (j + 1 <= i2)      pp = *(const float2*)(rp0b + j);
            else if (j >= i2 + 2) pp = *(const float2*)(rp1b + j);
            else { pp.x = posval(pb, i2, j); pp.y = posval(pb, i2, j + 1); }
            pr[nt][2] = pp.x; pr[nt][3] = pp.y;
        }

        if (kt < 15) {
            ISSUE(kt + 1, ST0_O + ((kt + 1) % 3) * ST_SZ);
            asm volatile("cp.async.wait_group 1;" ::: "memory");
        } else {
            asm volatile("cp.async.wait_group 0;" ::: "memory");
        }
        __syncthreads();   // buf kt visible; 3-stage ring keeps writer/readers disjoint

        // ---- S = Qu . K^T  (bf16x3, ldsm4-merged K loads) ----
        float sC[4][4] = {};
        #pragma unroll
        for (int ks = 0; ks < 4; ++ks) {
            uint32_t qh[4], ql[4], kh[2][4], kl[2][4];
            uint32_t qa = (wm * 16 + (lane & 15)) * 144 +
                          (ks * 16 + ((lane >> 4) << 3)) * 2;
            ldsm4(qh, sb + QUH_O + qa);
            ldsm4(ql, sb + QUL_O + qa);
            #pragma unroll
            for (int p = 0; p < 2; ++p) {
                uint32_t ao = (wn * 32 + p * 16 + (lane & 7) + ((lane >> 4) << 3)) * 144 +
                              (ks * 16 + (((lane >> 3) & 1) << 3)) * 2;
                ldsm4(kh[p], st + sb + ao);
                ldsm4(kl[p], st + sb + 9216 + ao);
            }
            #pragma unroll
            for (int p = 0; p < 2; ++p) {
                mma16816(sC[2*p],     qh, kh[p]);
                mma16816(sC[2*p],     qh, kl[p]);
                mma16816(sC[2*p],     ql, kh[p]);
                mma16816(sC[2*p + 1], qh, kh[p] + 2);
                mma16816(sC[2*p + 1], qh, kl[p] + 2);
                mma16816(sC[2*p + 1], ql, kh[p] + 2);
            }
        }

        // ---- exp(S + pos), pack into A fragments (no smem P) ----
        uint32_t aH[2][4], aL[2][4];
        #pragma unroll
        for (int nt = 0; nt < 4; ++nt) {
            float e0 = __expf(sC[nt][0] + pr[nt][0]);
            float e1 = __expf(sC[nt][1] + pr[nt][1]);
            float e2 = __expf(sC[nt][2] + pr[nt][2]);
            float e3 = __expf(sC[nt][3] + pr[nt][3]);
            ls[0] += e0 + e1;
            ls[1] += e2 + e3;
            const int kk = nt >> 1, half = (nt & 1) << 1;
            splitpair(e0, e1, aH[kk][half + 0], aL[kk][half + 0]);
            splitpair(e2, e3, aH[kk][half + 1], aL[kk][half + 1]);
        }

        // ---- O += P . V  (ldsm4-merged V loads; k-slice wn*32..+32) ----
        #pragma unroll
        for (int kk = 0; kk < 2; ++kk) {
            #pragma unroll
            for (int d2 = 0; d2 < 4; ++d2) {
                uint32_t vh[4], vl[4];
                uint32_t ao = (d2 * 16 + (lane & 7) + ((lane >> 4) << 3)) * 144 +
                              (wn * 32 + kk * 16 + (((lane >> 3) & 1) << 3)) * 2;
                ldsm4(vh, st + sb + 18432 + ao);
                ldsm4(vl, st + sb + 27648 + ao);
                mma16816(oC[2*d2],     aH[kk], vh);
                mma16816(oC[2*d2],     aH[kk], vl);
                mma16816(oC[2*d2],     aL[kk], vh);
                mma16816(oC[2*d2 + 1], aH[kk], vh + 2);
                mma16816(oC[2*d2 + 1], aH[kk], vl + 2);
                mma16816(oC[2*d2 + 1], aL[kk], vh + 2);
            }
        }
    }
    #undef ISSUE

    // ---- row-sum reduction: quad lanes, then the 2 wn warps via smem ----
    float* lsm = (float*)(cb + LS_O);
    #pragma unroll
    for (int p = 0; p < 2; ++p) {
        float vv = ls[p];
        vv += __shfl_xor_sync(0xffffffffu, vv, 1);
        vv += __shfl_xor_sync(0xffffffffu, vv, 2);
        ls[p] = vv;
    }
    if ((lane & 3) == 0) {
        lsm[wn * 128 + wm * 16 + g] = ls[0];
        lsm[wn * 128 + wm * 16 + 8 + g] = ls[1];
    }

    // ---- O partial reduction across the 2 wn warps (OB = buf1; last iter
    //      readers touch only buf0 = 15%3, so this is race-free pre-sync) ----
    float* ob = (float*)(cb + OB_O);
    if (wn == 1) {
        #pragma unroll
        for (int dn = 0; dn < 8; ++dn) {
            const int col = dn * 8 + (t4 << 1);
            *(float2*)&ob[(wm * 16 + g) * 64 + col] = make_float2(oC[dn][0], oC[dn][1]);
            *(float2*)&ob[(wm * 16 + 8 + g) * 64 + col] = make_float2(oC[dn][2], oC[dn][3]);
        }
    }
    __syncthreads();
    if (wn == 0) {
        const int r1 = wm * 16 + g, r2 = r1 + 8;
        const float inv1 = 1.0f / (lsm[r1] + lsm[128 + r1]);
        const float inv2 = 1.0f / (lsm[r2] + lsm[128 + r2]);
        float* ob1 = out + (size_t)n * 65536 + (size_t)(i0 + r1) * 64;
        float* ob2 = out + (size_t)n * 65536 + (size_t)(i0 + r2) * 64;
        #pragma unroll
        for (int dn = 0; dn < 8; ++dn) {
            const int col = dn * 8 + (t4 << 1);
            float2 p1 = *(float2*)&ob[r1 * 64 + col];
            float2 p2 = *(float2*)&ob[r2 * 64 + col];
            *(float2*)(ob1 + col) = make_float2((oC[dn][0] + p1.x) * inv1,
                                                (oC[dn][1] + p1.y) * inv1);
            *(float2*)(ob2 + col) = make_float2((oC[dn][2] + p2.x) * inv2,
                                                (oC[dn][3] + p2.y) * inv2);
        }
    }
}

// ---------------------------------------------------------------------------
extern "C" void kernel_launch(void* const* d_in, const int* in_sizes, int n_in,
                              void* d_out, int out_size)
{
    const float* q  = (const float*)d_in[0];
    const float* k  = (const float*)d_in[1];
    const float* v  = (const float*)d_in[2];
    const float* ub = (const float*)d_in[3];
    const float* vb = (const float*)d_in[4];
    const float* R  = (const float*)d_in[5];
    float* out = (float*)d_out;

    cudaFuncSetAttribute(pos_mma, cudaFuncAttributeMaxDynamicSharedMemorySize, POS_SMEM);
    cudaFuncSetAttribute(flash_mma, cudaFuncAttributeMaxDynamicSharedMemorySize, FLASH_SMEM);

    prep_kv<<<dim3(16, 64), 256>>>(k, v);
    prep_r<<<dim3(16, 16), 256>>>(R);
    pos_mma<<<dim3(16, 64), 256, POS_SMEM>>>(q, vb);
    flash_mma<<<dim3(8, 64), 512, FLASH_SMEM>>>(q, ub, out);
}

// round 13
// speedup vs baseline: 1.1942x; 1.1942x over previous
#include <cuda_runtime.h>
#include <cuda_bf16.h>
#include <cstdint>

#define PITCH 1026
// g_pos[n][i][t + s(i)], s(i)=(i+1)&1 -> flash shifted reads are 8B aligned
__device__ float g_pos[(size_t)64 * 1024 * PITCH];
// preconverted operands
__device__ __nv_bfloat16 g_kh[(size_t)64 * 1024 * 64];
__device__ __nv_bfloat16 g_kl[(size_t)64 * 1024 * 64];
__device__ __nv_bfloat16 g_vth[(size_t)64 * 64 * 1024];   // V^T: [n][d][j]
__device__ __nv_bfloat16 g_vtl[(size_t)64 * 64 * 1024];
__device__ __nv_bfloat16 g_rh[(size_t)16 * 1024 * 64];    // R hi: [h][t][d]
__device__ __nv_bfloat16 g_rl[(size_t)16 * 1024 * 64];

// ------------------------------ helpers -----------------------------------
__device__ __forceinline__ uint32_t smem_u32(const void* p) {
    uint32_t a;
    asm("{ .reg .u64 t; cvta.to.shared.u64 t, %1; cvt.u32.u64 %0, t; }" : "=r"(a) : "l"(p));
    return a;
}
__device__ __forceinline__ void ldsm4(uint32_t* r, uint32_t a) {
    asm volatile("ldmatrix.sync.aligned.m8n8.x4.shared.b16 {%0,%1,%2,%3}, [%4];"
        : "=r"(r[0]), "=r"(r[1]), "=r"(r[2]), "=r"(r[3]) : "r"(a));
}
__device__ __forceinline__ void mma16816(float* c, const uint32_t* a, const uint32_t* b) {
    asm volatile("mma.sync.aligned.m16n8k16.row.col.f32.bf16.bf16.f32 "
        "{%0,%1,%2,%3}, {%4,%5,%6,%7}, {%8,%9}, {%0,%1,%2,%3};"
        : "+f"(c[0]), "+f"(c[1]), "+f"(c[2]), "+f"(c[3])
        : "r"(a[0]), "r"(a[1]), "r"(a[2]), "r"(a[3]), "r"(b[0]), "r"(b[1]));
}
// fast packed split: hi = bf16x2(a,b) (a in low half), lo = bf16x2 of residuals.
// Bit-identical to per-element __float2bfloat16_rn + pack.
__device__ __forceinline__ void splitpair(float a, float b, uint32_t& hi, uint32_t& lo) {
    uint32_t h;
    asm("cvt.rn.bf16x2.f32 %0, %1, %2;" : "=r"(h) : "f"(b), "f"(a));
    float ah = __uint_as_float(h << 16);
    float bh = __uint_as_float(h & 0xffff0000u);
    float la = a - ah, lb = b - bh;
    uint32_t l;
    asm("cvt.rn.bf16x2.f32 %0, %1, %2;" : "=r"(l) : "f"(lb), "f"(la));
    hi = h; lo = l;
}
__device__ __forceinline__ float posval(const float* pb, int i, int j) {
    if (j <= i)     return pb[(size_t)i * PITCH + (1023 + j - i + ((i + 1) & 1))];
    if (j == i + 1) return 0.0f;
    return pb[(size_t)(i + 1) * PITCH + (j - i - 2 + ((i + 2) & 1))];
}
__device__ __forceinline__ float2 pos2(const float* pb, int i, int j) {
    if (j + 1 <= i)
        return *(const float2*)(pb + (size_t)i * PITCH + (1023 - i + ((i + 1) & 1)) + j);
    if (j >= i + 2)
        return *(const float2*)(pb + (size_t)(i + 1) * PITCH + (((i + 2) & 1) - i - 2) + j);
    float2 r;
    r.x = posval(pb, i, j);
    r.y = posval(pb, i, j + 1);
    return r;
}
#define CPA16(dst, src) asm volatile("cp.async.cg.shared.global [%0], [%1], 16;" :: "r"(dst), "l"(src))
#define CPA_COMMIT()    asm volatile("cp.async.commit_group;" ::: "memory")

// ---------------------------------------------------------------------------
// Kernel 0a: preconvert K -> (hi,lo) bf16 [n][j][d]; V -> transposed (hi,lo)
// bf16 [n][d][j]. grid (16 jt, 64 n), 256 thr.
// ---------------------------------------------------------------------------
__global__ __launch_bounds__(256)
void prep_kv(const float* __restrict__ k, const float* __restrict__ v)
{
    __shared__ float vs[64 * 65];
    const int tid = threadIdx.x, n = blockIdx.y, jt = blockIdx.x;
    const float* kb = k + (size_t)n * 65536 + jt * 4096;
    const float* vb = v + (size_t)n * 65536 + jt * 4096;

    #pragma unroll
    for (int it = 0; it < 4; ++it) {
        int fi = it * 256 + tid;
        int r = fi >> 4, d = (fi & 15) << 2;
        float4 f = *(const float4*)(kb + r * 64 + d);
        uint32_t h0, l0, h1, l1;
        splitpair(f.x, f.y, h0, l0); splitpair(f.z, f.w, h1, l1);
        size_t o = (((size_t)n * 1024 + jt * 64 + r) << 6) + d;
        *(uint2*)(g_kh + o) = make_uint2(h0, h1);
        *(uint2*)(g_kl + o) = make_uint2(l0, l1);
        float4 g = *(const float4*)(vb + r * 64 + d);
        vs[r * 65 + d + 0] = g.x; vs[r * 65 + d + 1] = g.y;
        vs[r * 65 + d + 2] = g.z; vs[r * 65 + d + 3] = g.w;
    }
    __syncthreads();
    #pragma unroll
    for (int it = 0; it < 4; ++it) {
        int fi = it * 256 + tid;
        int d = fi >> 4, j = (fi & 15) << 2;
        float a0 = vs[(j + 0) * 65 + d], a1 = vs[(j + 1) * 65 + d];
        float a2 = vs[(j + 2) * 65 + d], a3 = vs[(j + 3) * 65 + d];
        uint32_t h0, l0, h1, l1;
        splitpair(a0, a1, h0, l0); splitpair(a2, a3, h1, l1);
        size_t o = (((size_t)n * 64 + d) << 10) + jt * 64 + j;
        *(uint2*)(g_vth + o) = make_uint2(h0, h1);
        *(uint2*)(g_vtl + o) = make_uint2(l0, l1);
    }
}

// ---------------------------------------------------------------------------
// Kernel 0b: preconvert R -> (hi,lo) bf16 [h][t][d], t < 1024. grid (16 tt, 16 h).
// ---------------------------------------------------------------------------
__global__ __launch_bounds__(256)
void prep_r(const float* __restrict__ R)
{
    const int tid = threadIdx.x, h = blockIdx.y, tt = blockIdx.x;
    const float* rb = R + (size_t)h * (2048 * 64) + tt * 4096;
    #pragma unroll
    for (int it = 0; it < 4; ++it) {
        int fi = it * 256 + tid;
        int r = fi >> 4, d = (fi & 15) << 2;
        float4 f = *(const float4*)(rb + r * 64 + d);
        uint32_t h0, l0, h1, l1;
        splitpair(f.x, f.y, h0, l0); splitpair(f.z, f.w, h1, l1);
        size_t o = (((size_t)h * 1024 + tt * 64 + r) << 6) + d;
        *(uint2*)(g_rh + o) = make_uint2(h0, h1);
        *(uint2*)(g_rl + o) = make_uint2(l0, l1);
    }
}

// ---------------------------------------------------------------------------
// Kernel 1: g_pos(shifted) = (q*0.125 + vbias) . R^T  via mma.sync bf16x3.
// v3 (R11): BM=64, grid (16 i, 64 n), 256 thr = 8 warps 4(M)x2(N);
// 3-stage cp.async R buffers, smem-staged coalesced epilogue (2 syncs/iter).
// ---------------------------------------------------------------------------
#define PQH 0
#define PQL 9216
#define PRB 18432            /* 3 bufs of 18432 (hi 0, lo +9216) */
#define PPS 73728            /* Ps: 64 x 68 fp32 = 17408 */
#define POS_SMEM 91136

__global__ __launch_bounds__(256)
void pos_mma(const float* __restrict__ q, const float* __restrict__ vbias)
{
    extern __shared__ char cb[];
    uint32_t sb = smem_u32(cb);

    const int tid = threadIdx.x, lane = tid & 31, wid = tid >> 5;
    const int wm = wid >> 1, wn = wid & 1;       // 4 M-groups x 2 N-groups
    const int n = blockIdx.y, h = n & 15;
    const int i0 = blockIdx.x << 6;

    // stage Qv = q*0.125 + vbias (hi/lo) once: 64 rows
    const float* qb = q + (size_t)n * 65536 + (size_t)i0 * 64;
    #pragma unroll
    for (int it = 0; it < 4; ++it) {
        int fi = it * 256 + tid;
        int r = fi >> 4, d = (fi & 15) << 2;
        float4 f = *(const float4*)(qb + r * 64 + d);
        float4 bs = *(const float4*)(vbias + h * 64 + d);
        f.x = f.x * 0.125f + bs.x; f.y = f.y * 0.125f + bs.y;
        f.z = f.z * 0.125f + bs.z; f.w = f.w * 0.125f + bs.w;
        uint2 H, L;
        splitpair(f.x, f.y, H.x, L.x); splitpair(f.z, f.w, H.y, L.y);
        *(uint2*)(cb + PQH + r * 144 + d * 2) = H;
        *(uint2*)(cb + PQL + r * 144 + d * 2) = L;
    }

    const char* ghb = (const char*)(g_rh + ((size_t)h << 16));
    const char* glb = (const char*)(g_rl + ((size_t)h << 16));

    #define ISSUE_R(kt, base) do {                                             \
        const char* _gh = ghb + ((size_t)(kt) << 13);                          \
        const char* _gl = glb + ((size_t)(kt) << 13);                          \
        _Pragma("unroll")                                                      \
        for (int c = tid; c < 512; c += 256) {                                 \
            uint32_t so = (uint32_t)((c >> 3) * 144 + ((c & 7) << 4));         \
            uint32_t go = (uint32_t)(((c >> 3) << 7) + ((c & 7) << 4));        \
            CPA16(sb + (base) + so, _gh + go);                                 \
            CPA16(sb + (base) + 9216 + so, _gl + go);                         \
        }                                                                      \
        CPA_COMMIT();                                                          \
    } while (0)

    ISSUE_R(0, PRB);

    float* gpn = g_pos + (size_t)n * (1024 * PITCH);
    float* Ps = (float*)(cb + PPS);

    for (int kt = 0; kt < 16; ++kt) {
        const uint32_t rB = PRB + (kt % 3) * 18432;
        if (kt < 15) {
            ISSUE_R(kt + 1, PRB + ((kt + 1) % 3) * 18432);
            asm volatile("cp.async.wait_group 1;" ::: "memory");
        } else {
            asm volatile("cp.async.wait_group 0;" ::: "memory");
        }
        __syncthreads();   // buf kt visible to all; prev Ps reads done

        // ---- C = Qv . R^T (bf16x3); warp tile 16(i) x 32(t) ----
        float sC[4][4] = {};
        #pragma unroll
        for (int ks = 0; ks < 4; ++ks) {
            uint32_t qh[4], ql[4], rh[2][4], rl[2][4];
            uint32_t qa = (wm * 16 + (lane & 15)) * 144 +
                          (ks * 16 + ((lane >> 4) << 3)) * 2;
            ldsm4(qh, sb + PQH + qa);
            ldsm4(ql, sb + PQL + qa);
            #pragma unroll
            for (int p = 0; p < 2; ++p) {
                uint32_t ao = (wn * 32 + p * 16 + (lane & 7) + ((lane >> 4) << 3)) * 144 +
                              (ks * 16 + (((lane >> 3) & 1) << 3)) * 2;
                ldsm4(rh[p], sb + rB + ao);
                ldsm4(rl[p], sb + rB + 9216 + ao);
            }
            #pragma unroll
            for (int p = 0; p < 2; ++p) {
                mma16816(sC[2*p],     qh, rh[p]);
                mma16816(sC[2*p],     qh, rl[p]);
                mma16816(sC[2*p],     ql, rh[p]);
                mma16816(sC[2*p + 1], qh, rh[p] + 2);
                mma16816(sC[2*p + 1], qh, rl[p] + 2);
                mma16816(sC[2*p + 1], ql, rh[p] + 2);
            }
        }

        // ---- stage C in Ps, then coalesced shifted write ----
        #pragma unroll
        for (int nt = 0; nt < 4; ++nt) {
            const int r1 = wm * 16 + (lane >> 2);
            const int c = wn * 32 + nt * 8 + ((lane & 3) << 1);
            Ps[r1 * 68 + c]           = sC[nt][0];
            Ps[r1 * 68 + c + 1]       = sC[nt][1];
            Ps[(r1 + 8) * 68 + c]     = sC[nt][2];
            Ps[(r1 + 8) * 68 + c + 1] = sC[nt][3];
        }
        __syncthreads();
        const int t0 = kt << 6;
        #pragma unroll
        for (int rr = 0; rr < 8; ++rr) {
            const int r = (wid << 3) + rr;
            const int i = i0 + r;
            float* gp = gpn + (size_t)i * PITCH + t0 + ((i + 1) & 1);
            gp[lane]      = Ps[r * 68 + lane];
            gp[lane + 32] = Ps[r * 68 + lane + 32];
        }
    }
    #undef ISSUE_R
}

// ---------------------------------------------------------------------------
// Kernel 2: flash attention, bf16x3, P in registers, 3-stage cp.async pipeline,
// ONE __syncthreads per iteration. BM=128(i), BN=64(j), 16 iters.
// 512 thr = 16 warps as 8(M)x2(N). grid (8 i-tiles, 64 n).
// ---------------------------------------------------------------------------
#define QUH_O 0
#define QUL_O 18432
#define ST0_O 36864          /* stage: KH 0 | KL 9216 | VTH 18432 | VTL 27648 */
#define ST_SZ 36864
#define LS_O  (ST0_O + 3 * ST_SZ)      /* 147456 */
#define OB_O  (ST0_O + ST_SZ)          /* buf1 overlay (last iter reads buf0) */
#define FLASH_SMEM (LS_O + 1024)       /* 148480 */

__global__ __launch_bounds__(512)
void flash_mma(const float* __restrict__ q, const float* __restrict__ ubias,
               float* __restrict__ out)
{
    extern __shared__ char cb[];
    uint32_t sb = smem_u32(cb);

    const int tid = threadIdx.x, lane = tid & 31, wid = tid >> 5;
    const int wm = wid >> 1, wn = wid & 1;       // 8 M-rows x 2 N-cols
    const int n = blockIdx.y, h = n & 15;
    const int i0 = blockIdx.x << 7;

    // stage Qu = q*0.125 + u_bias (hi/lo)
    const float* qb = q + (size_t)n * 65536 + (size_t)i0 * 64;
    #pragma unroll
    for (int it = 0; it < 4; ++it) {
        int fi = it * 512 + tid;
        int r = fi >> 4, d = (fi & 15) << 2;
        float4 f = *(const float4*)(qb + r * 64 + d);
        float4 bs = *(const float4*)(ubias + h * 64 + d);
        f.x = f.x * 0.125f + bs.x; f.y = f.y * 0.125f + bs.y;
        f.z = f.z * 0.125f + bs.z; f.w = f.w * 0.125f + bs.w;
        uint2 H, L;
        splitpair(f.x, f.y, H.x, L.x); splitpair(f.z, f.w, H.y, L.y);
        *(uint2*)(cb + QUH_O + r * 144 + d * 2) = H;
        *(uint2*)(cb + QUL_O + r * 144 + d * 2) = L;
    }

    float oC[8][4] = {};
    float ls[2] = {};
    const float* pb = g_pos + (size_t)n * (1024 * PITCH);

    const int g = lane >> 2, t4 = lane & 3;
    const int i1 = i0 + wm * 16 + g;
    const int i2 = i1 + 8;

    const int cr = tid >> 3;
    const int coff = (tid & 7) << 4;
    const char* khb = (const char*)(g_kh + (((size_t)n * 1024 + cr) << 6)) + coff;
    const char* klb = (const char*)(g_kl + (((size_t)n * 1024 + cr) << 6)) + coff;
    const char* vhb = (const char*)(g_vth + (((size_t)n * 64 + cr) << 10)) + coff;
    const char* vlb = (const char*)(g_vtl + (((size_t)n * 64 + cr) << 10)) + coff;
    const uint32_t sdst = sb + cr * 144 + coff;

    #define ISSUE(kt, st) do {                                              \
        CPA16(sdst + (st) + 0,     khb + ((size_t)(kt) << 13));             \
        CPA16(sdst + (st) + 9216,  klb + ((size_t)(kt) << 13));             \
        CPA16(sdst + (st) + 18432, vhb + ((size_t)(kt) << 7));              \
        CPA16(sdst + (st) + 27648, vlb + ((size_t)(kt) << 7));              \
        CPA_COMMIT();                                                       \
    } while (0)

    ISSUE(0, ST0_O);

    for (int kt = 0; kt < 16; ++kt) {
        const uint32_t st = ST0_O + (kt % 3) * ST_SZ;

        // ---- prefetch shifted pos values (overlaps cp.async + compute) ----
        float pr[4][4];
        #pragma unroll
        for (int nt = 0; nt < 4; ++nt) {
            const int j = (kt << 6) + wn * 32 + nt * 8 + (t4 << 1);
            float2 pp = pos2(pb, i1, j);
            pr[nt][0] = pp.x; pr[nt][1] = pp.y;
            pp = pos2(pb, i2, j);
            pr[nt][2] = pp.x; pr[nt][3] = pp.y;
        }

        if (kt < 15) {
            ISSUE(kt + 1, ST0_O + ((kt + 1) % 3) * ST_SZ);
            asm volatile("cp.async.wait_group 1;" ::: "memory");
        } else {
            asm volatile("cp.async.wait_group 0;" ::: "memory");
        }
        __syncthreads();   // buf kt visible; 3-stage ring keeps writer/readers disjoint

        // ---- S = Qu . K^T  (bf16x3, ldsm4-merged K loads) ----
        float sC[4][4] = {};
        #pragma unroll
        for (int ks = 0; ks < 4; ++ks) {
            uint32_t qh[4], ql[4], kh[2][4], kl[2][4];
            uint32_t qa = (wm * 16 + (lane & 15)) * 144 +
                          (ks * 16 + ((lane >> 4) << 3)) * 2;
            ldsm4(qh, sb + QUH_O + qa);
            ldsm4(ql, sb + QUL_O + qa);
            #pragma unroll
            for (int p = 0; p < 2; ++p) {
                uint32_t ao = (wn * 32 + p * 16 + (lane & 7) + ((lane >> 4) << 3)) * 144 +
                              (ks * 16 + (((lane >> 3) & 1) << 3)) * 2;
                ldsm4(kh[p], st + sb + ao);
                ldsm4(kl[p], st + sb + 9216 + ao);
            }
            #pragma unroll
            for (int p = 0; p < 2; ++p) {
                mma16816(sC[2*p],     qh, kh[p]);
                mma16816(sC[2*p],     qh, kl[p]);
                mma16816(sC[2*p],     ql, kh[p]);
                mma16816(sC[2*p + 1], qh, kh[p] + 2);
                mma16816(sC[2*p + 1], qh, kl[p] + 2);
                mma16816(sC[2*p + 1], ql, kh[p] + 2);
            }
        }

        // ---- exp(S + pos), pack into A fragments (no smem P) ----
        uint32_t aH[2][4], aL[2][4];
        #pragma unroll
        for (int nt = 0; nt < 4; ++nt) {
            float e0 = __expf(sC[nt][0] + pr[nt][0]);
            float e1 = __expf(sC[nt][1] + pr[nt][1]);
            float e2 = __expf(sC[nt][2] + pr[nt][2]);
            float e3 = __expf(sC[nt][3] + pr[nt][3]);
            ls[0] += e0 + e1;
            ls[1] += e2 + e3;
            const int kk = nt >> 1, half = (nt & 1) << 1;
            splitpair(e0, e1, aH[kk][half + 0], aL[kk][half + 0]);
            splitpair(e2, e3, aH[kk][half + 1], aL[kk][half + 1]);
        }

        // ---- O += P . V  (ldsm4-merged V loads; k-slice wn*32..+32) ----
        #pragma unroll
        for (int kk = 0; kk < 2; ++kk) {
            #pragma unroll
            for (int d2 = 0; d2 < 4; ++d2) {
                uint32_t vh[4], vl[4];
                uint32_t ao = (d2 * 16 + (lane & 7) + ((lane >> 4) << 3)) * 144 +
                              (wn * 32 + kk * 16 + (((lane >> 3) & 1) << 3)) * 2;
                ldsm4(vh, st + sb + 18432 + ao);
                ldsm4(vl, st + sb + 27648 + ao);
                mma16816(oC[2*d2],     aH[kk], vh);
                mma16816(oC[2*d2],     aH[kk], vl);
                mma16816(oC[2*d2],     aL[kk], vh);
                mma16816(oC[2*d2 + 1], aH[kk], vh + 2);
                mma16816(oC[2*d2 + 1], aH[kk], vl + 2);
                mma16816(oC[2*d2 + 1], aL[kk], vh + 2);
            }
        }
    }
    #undef ISSUE

    // ---- row-sum reduction: quad lanes, then the 2 wn warps via smem ----
    float* lsm = (float*)(cb + LS_O);
    #pragma unroll
    for (int p = 0; p < 2; ++p) {
        float vv = ls[p];
        vv += __shfl_xor_sync(0xffffffffu, vv, 1);
        vv += __shfl_xor_sync(0xffffffffu, vv, 2);
        ls[p] = vv;
    }
    if ((lane & 3) == 0) {
        lsm[wn * 128 + wm * 16 + g] = ls[0];
        lsm[wn * 128 + wm * 16 + 8 + g] = ls[1];
    }

    // ---- O partial reduction across the 2 wn warps (OB = buf1; last iter
    //      readers touch only buf0 = 15%3, so this is race-free pre-sync) ----
    float* ob = (float*)(cb + OB_O);
    if (wn == 1) {
        #pragma unroll
        for (int dn = 0; dn < 8; ++dn) {
            const int col = dn * 8 + (t4 << 1);
            *(float2*)&ob[(wm * 16 + g) * 64 + col] = make_float2(oC[dn][0], oC[dn][1]);
            *(float2*)&ob[(wm * 16 + 8 + g) * 64 + col] = make_float2(oC[dn][2], oC[dn][3]);
        }
    }
    __syncthreads();
    if (wn == 0) {
        const int r1 = wm * 16 + g, r2 = r1 + 8;
        const float inv1 = 1.0f / (lsm[r1] + lsm[128 + r1]);
        const float inv2 = 1.0f / (lsm[r2] + lsm[128 + r2]);
        float* ob1 = out + (size_t)n * 65536 + (size_t)(i0 + r1) * 64;
        float* ob2 = out + (size_t)n * 65536 + (size_t)(i0 + r2) * 64;
        #pragma unroll
        for (int dn = 0; dn < 8; ++dn) {
            const int col = dn * 8 + (t4 << 1);
            float2 p1 = *(float2*)&ob[r1 * 64 + col];
            float2 p2 = *(float2*)&ob[r2 * 64 + col];
            *(float2*)(ob1 + col) = make_float2((oC[dn][0] + p1.x) * inv1,
                                                (oC[dn][1] + p1.y) * inv1);
            *(float2*)(ob2 + col) = make_float2((oC[dn][2] + p2.x) * inv2,
                                                (oC[dn][3] + p2.y) * inv2);
        }
    }
}

// ---------------------------------------------------------------------------
extern "C" void kernel_launch(void* const* d_in, const int* in_sizes, int n_in,
                              void* d_out, int out_size)
{
    const float* q  = (const float*)d_in[0];
    const float* k  = (const float*)d_in[1];
    const float* v  = (const float*)d_in[2];
    const float* ub = (const float*)d_in[3];
    const float* vb = (const float*)d_in[4];
    const float* R  = (const float*)d_in[5];
    float* out = (float*)d_out;

    cudaFuncSetAttribute(pos_mma, cudaFuncAttributeMaxDynamicSharedMemorySize, POS_SMEM);
    cudaFuncSetAttribute(flash_mma, cudaFuncAttributeMaxDynamicSharedMemorySize, FLASH_SMEM);

    prep_kv<<<dim3(16, 64), 256>>>(k, v);
    prep_r<<<dim3(16, 16), 256>>>(R);
    pos_mma<<<dim3(16, 64), 256, POS_SMEM>>>(q, vb);
    flash_mma<<<dim3(8, 64), 512, FLASH_SMEM>>>(q, ub, out);
}

// round 14
// speedup vs baseline: 1.3293x; 1.1132x over previous
#include <cuda_runtime.h>
#include <cuda_bf16.h>
#include <cstdint>

#define PITCH 1026
// g_pos[n][i][t + s(i)], s(i)=(i+1)&1 -> flash shifted reads are 8B aligned
__device__ float g_pos[(size_t)64 * 1024 * PITCH];
// preconverted operands
__device__ __nv_bfloat16 g_kh[(size_t)64 * 1024 * 64];
__device__ __nv_bfloat16 g_kl[(size_t)64 * 1024 * 64];
__device__ __nv_bfloat16 g_vth[(size_t)64 * 64 * 1024];   // V^T: [n][d][j]
__device__ __nv_bfloat16 g_vtl[(size_t)64 * 64 * 1024];
__device__ __nv_bfloat16 g_rh[(size_t)16 * 1024 * 64];    // R hi: [h][t][d]
__device__ __nv_bfloat16 g_rl[(size_t)16 * 1024 * 64];

// ------------------------------ helpers -----------------------------------
__device__ __forceinline__ uint32_t smem_u32(const void* p) {
    uint32_t a;
    asm("{ .reg .u64 t; cvta.to.shared.u64 t, %1; cvt.u32.u64 %0, t; }" : "=r"(a) : "l"(p));
    return a;
}
__device__ __forceinline__ void ldsm4(uint32_t* r, uint32_t a) {
    asm volatile("ldmatrix.sync.aligned.m8n8.x4.shared.b16 {%0,%1,%2,%3}, [%4];"
        : "=r"(r[0]), "=r"(r[1]), "=r"(r[2]), "=r"(r[3]) : "r"(a));
}
__device__ __forceinline__ void mma16816(float* c, const uint32_t* a, const uint32_t* b) {
    asm volatile("mma.sync.aligned.m16n8k16.row.col.f32.bf16.bf16.f32 "
        "{%0,%1,%2,%3}, {%4,%5,%6,%7}, {%8,%9}, {%0,%1,%2,%3};"
        : "+f"(c[0]), "+f"(c[1]), "+f"(c[2]), "+f"(c[3])
        : "r"(a[0]), "r"(a[1]), "r"(a[2]), "r"(a[3]), "r"(b[0]), "r"(b[1]));
}
// packed split: hi = bf16x2(a,b) (a low), lo = bf16x2 of residuals (bit-identical
// to per-element __float2bfloat16_rn + pack).
__device__ __forceinline__ void splitpair(float a, float b, uint32_t& hi, uint32_t& lo) {
    uint32_t h;
    asm("cvt.rn.bf16x2.f32 %0, %1, %2;" : "=r"(h) : "f"(b), "f"(a));
    float ah = __uint_as_float(h << 16);
    float bh = __uint_as_float(h & 0xffff0000u);
    float la = a - ah, lb = b - bh;
    uint32_t l;
    asm("cvt.rn.bf16x2.f32 %0, %1, %2;" : "=r"(l) : "f"(lb), "f"(la));
    hi = h; lo = l;
}
__device__ __forceinline__ float posval(const float* pb, int i, int j) {
    if (j <= i)     return pb[(size_t)i * PITCH + (1023 + j - i + ((i + 1) & 1))];
    if (j == i + 1) return 0.0f;
    return pb[(size_t)(i + 1) * PITCH + (j - i - 2 + ((i + 2) & 1))];
}
__device__ __forceinline__ float2 pos2(const float* pb, int i, int j) {
    if (j + 1 <= i)
        return *(const float2*)(pb + (size_t)i * PITCH + (1023 - i + ((i + 1) & 1)) + j);
    if (j >= i + 2)
        return *(const float2*)(pb + (size_t)(i + 1) * PITCH + (((i + 2) & 1) - i - 2) + j);
    float2 r;
    r.x = posval(pb, i, j);
    r.y = posval(pb, i, j + 1);
    return r;
}
#define CPA16(dst, src) asm volatile("cp.async.cg.shared.global [%0], [%1], 16;" :: "r"(dst), "l"(src))
#define CPA_COMMIT()    asm volatile("cp.async.commit_group;" ::: "memory")

// ---------------------------------------------------------------------------
// Kernel 0a: preconvert K -> (hi,lo) bf16 [n][j][d]; V -> transposed (hi,lo)
// bf16 [n][d][j]. grid (16 jt, 64 n), 256 thr.
// ---------------------------------------------------------------------------
__global__ __launch_bounds__(256)
void prep_kv(const float* __restrict__ k, const float* __restrict__ v)
{
    __shared__ float vs[64 * 65];
    const int tid = threadIdx.x, n = blockIdx.y, jt = blockIdx.x;
    const float* kb = k + (size_t)n * 65536 + jt * 4096;
    const float* vb = v + (size_t)n * 65536 + jt * 4096;

    #pragma unroll
    for (int it = 0; it < 4; ++it) {
        int fi = it * 256 + tid;
        int r = fi >> 4, d = (fi & 15) << 2;
        float4 f = *(const float4*)(kb + r * 64 + d);
        uint32_t h0, l0, h1, l1;
        splitpair(f.x, f.y, h0, l0); splitpair(f.z, f.w, h1, l1);
        size_t o = (((size_t)n * 1024 + jt * 64 + r) << 6) + d;
        *(uint2*)(g_kh + o) = make_uint2(h0, h1);
        *(uint2*)(g_kl + o) = make_uint2(l0, l1);
        float4 g = *(const float4*)(vb + r * 64 + d);
        vs[r * 65 + d + 0] = g.x; vs[r * 65 + d + 1] = g.y;
        vs[r * 65 + d + 2] = g.z; vs[r * 65 + d + 3] = g.w;
    }
    __syncthreads();
    #pragma unroll
    for (int it = 0; it < 4; ++it) {
        int fi = it * 256 + tid;
        int d = fi >> 4, j = (fi & 15) << 2;
        float a0 = vs[(j + 0) * 65 + d], a1 = vs[(j + 1) * 65 + d];
        float a2 = vs[(j + 2) * 65 + d], a3 = vs[(j + 3) * 65 + d];
        uint32_t h0, l0, h1, l1;
        splitpair(a0, a1, h0, l0); splitpair(a2, a3, h1, l1);
        size_t o = (((size_t)n * 64 + d) << 10) + jt * 64 + j;
        *(uint2*)(g_vth + o) = make_uint2(h0, h1);
        *(uint2*)(g_vtl + o) = make_uint2(l0, l1);
    }
}

// ---------------------------------------------------------------------------
// Kernel 0b: preconvert R -> (hi,lo) bf16 [h][t][d], t < 1024. grid (16 tt, 16 h).
// ---------------------------------------------------------------------------
__global__ __launch_bounds__(256)
void prep_r(const float* __restrict__ R)
{
    const int tid = threadIdx.x, h = blockIdx.y, tt = blockIdx.x;
    const float* rb = R + (size_t)h * (2048 * 64) + tt * 4096;
    #pragma unroll
    for (int it = 0; it < 4; ++it) {
        int fi = it * 256 + tid;
        int r = fi >> 4, d = (fi & 15) << 2;
        float4 f = *(const float4*)(rb + r * 64 + d);
        uint32_t h0, l0, h1, l1;
        splitpair(f.x, f.y, h0, l0); splitpair(f.z, f.w, h1, l1);
        size_t o = (((size_t)h * 1024 + tt * 64 + r) << 6) + d;
        *(uint2*)(g_rh + o) = make_uint2(h0, h1);
        *(uint2*)(g_rl + o) = make_uint2(l0, l1);
    }
}

// ---------------------------------------------------------------------------
// Kernel 1: g_pos(shifted) = (q*0.125 + vbias) . R^T  via mma.sync bf16x3.
// v3 (R11): BM=64, grid (16 i, 64 n), 256 thr = 8 warps 4(M)x2(N);
// 3-stage cp.async R buffers, smem-staged coalesced epilogue.
// ---------------------------------------------------------------------------
#define PQH 0
#define PQL 9216
#define PRB 18432            /* 3 bufs of 18432 (hi 0, lo +9216) */
#define PPS 73728            /* Ps: 64 x 68 fp32 = 17408 */
#define POS_SMEM 91136

__global__ __launch_bounds__(256)
void pos_mma(const float* __restrict__ q, const float* __restrict__ vbias)
{
    extern __shared__ char cb[];
    uint32_t sb = smem_u32(cb);

    const int tid = threadIdx.x, lane = tid & 31, wid = tid >> 5;
    const int wm = wid >> 1, wn = wid & 1;       // 4 M-groups x 2 N-groups
    const int n = blockIdx.y, h = n & 15;
    const int i0 = blockIdx.x << 6;

    // stage Qv = q*0.125 + vbias (hi/lo) once: 64 rows
    const float* qb = q + (size_t)n * 65536 + (size_t)i0 * 64;
    #pragma unroll
    for (int it = 0; it < 4; ++it) {
        int fi = it * 256 + tid;
        int r = fi >> 4, d = (fi & 15) << 2;
        float4 f = *(const float4*)(qb + r * 64 + d);
        float4 bs = *(const float4*)(vbias + h * 64 + d);
        f.x = f.x * 0.125f + bs.x; f.y = f.y * 0.125f + bs.y;
        f.z = f.z * 0.125f + bs.z; f.w = f.w * 0.125f + bs.w;
        uint2 H, L;
        splitpair(f.x, f.y, H.x, L.x); splitpair(f.z, f.w, H.y, L.y);
        *(uint2*)(cb + PQH + r * 144 + d * 2) = H;
        *(uint2*)(cb + PQL + r * 144 + d * 2) = L;
    }

    const char* ghb = (const char*)(g_rh + ((size_t)h << 16));
    const char* glb = (const char*)(g_rl + ((size_t)h << 16));

    #define ISSUE_R(kt, base) do {                                             \
        const char* _gh = ghb + ((size_t)(kt) << 13);                          \
        const char* _gl = glb + ((size_t)(kt) << 13);                          \
        _Pragma("unroll")                                                      \
        for (int c = tid; c < 512; c += 256) {                                 \
            uint32_t so = (uint32_t)((c >> 3) * 144 + ((c & 7) << 4));         \
            uint32_t go = (uint32_t)(((c >> 3) << 7) + ((c & 7) << 4));        \
            CPA16(sb + (base) + so, _gh + go);                                 \
            CPA16(sb + (base) + 9216 + so, _gl + go);                         \
        }                                                                      \
        CPA_COMMIT();                                                          \
    } while (0)

    ISSUE_R(0, PRB);

    float* gpn = g_pos + (size_t)n * (1024 * PITCH);
    float* Ps = (float*)(cb + PPS);

    for (int kt = 0; kt < 16; ++kt) {
        const uint32_t rB = PRB + (kt % 3) * 18432;
        if (kt < 15) {
            ISSUE_R(kt + 1, PRB + ((kt + 1) % 3) * 18432);
            asm volatile("cp.async.wait_group 1;" ::: "memory");
        } else {
            asm volatile("cp.async.wait_group 0;" ::: "memory");
        }
        __syncthreads();   // buf kt visible to all; prev Ps reads done

        // ---- C = Qv . R^T (bf16x3); warp tile 16(i) x 32(t) ----
        float sC[4][4] = {};
        #pragma unroll
        for (int ks = 0; ks < 4; ++ks) {
            uint32_t qh[4], ql[4], rh[2][4], rl[2][4];
            uint32_t qa = (wm * 16 + (lane & 15)) * 144 +
                          (ks * 16 + ((lane >> 4) << 3)) * 2;
            ldsm4(qh, sb + PQH + qa);
            ldsm4(ql, sb + PQL + qa);
            #pragma unroll
            for (int p = 0; p < 2; ++p) {
                uint32_t ao = (wn * 32 + p * 16 + (lane & 7) + ((lane >> 4) << 3)) * 144 +
                              (ks * 16 + (((lane >> 3) & 1) << 3)) * 2;
                ldsm4(rh[p], sb + rB + ao);
                ldsm4(rl[p], sb + rB + 9216 + ao);
            }
            #pragma unroll
            for (int p = 0; p < 2; ++p) {
                mma16816(sC[2*p],     qh, rh[p]);
                mma16816(sC[2*p],     qh, rl[p]);
                mma16816(sC[2*p],     ql, rh[p]);
                mma16816(sC[2*p + 1], qh, rh[p] + 2);
                mma16816(sC[2*p + 1], qh, rl[p] + 2);
                mma16816(sC[2*p + 1], ql, rh[p] + 2);
            }
        }

        // ---- stage C in Ps, then coalesced shifted write ----
        #pragma unroll
        for (int nt = 0; nt < 4; ++nt) {
            const int r1 = wm * 16 + (lane >> 2);
            const int c = wn * 32 + nt * 8 + ((lane & 3) << 1);
            Ps[r1 * 68 + c]           = sC[nt][0];
            Ps[r1 * 68 + c + 1]       = sC[nt][1];
            Ps[(r1 + 8) * 68 + c]     = sC[nt][2];
            Ps[(r1 + 8) * 68 + c + 1] = sC[nt][3];
        }
        __syncthreads();
        const int t0 = kt << 6;
        #pragma unroll
        for (int rr = 0; rr < 8; ++rr) {
            const int r = (wid << 3) + rr;
            const int i = i0 + r;
            float* gp = gpn + (size_t)i * PITCH + t0 + ((i + 1) & 1);
            gp[lane]      = Ps[r * 68 + lane];
            gp[lane + 32] = Ps[r * 68 + lane + 32];
        }
    }
    #undef ISSUE_R
}

// ---------------------------------------------------------------------------
// Kernel 2: flash attention v4: 256 thr = 8 warps 4(M)x2(N), BM=64, BN=64,
// 2-stage cp.async ring, ONE sync/iter (issue AFTER barrier -> no 3rd buffer
// needed), 2 CTAs/SM for cross-CTA latency hiding. grid (16 i-tiles, 64 n).
// ---------------------------------------------------------------------------
#define QUH_O 0
#define QUL_O 9216
#define ST0_O 18432          /* stage: KH 0 | KL 9216 | VTH 18432 | VTL 27648 */
#define ST_SZ 36864
#define LS_O  (ST0_O + 2 * ST_SZ)      /* 92160 */
#define OB_O  ST0_O                    /* buf0 overlay (last iter reads buf1) */
#define FLASH_SMEM (LS_O + 1024)       /* 93184 -> 2 CTAs/SM */

__global__ __launch_bounds__(256)
void flash_mma(const float* __restrict__ q, const float* __restrict__ ubias,
               float* __restrict__ out)
{
    extern __shared__ char cb[];
    uint32_t sb = smem_u32(cb);

    const int tid = threadIdx.x, lane = tid & 31, wid = tid >> 5;
    const int wm = wid >> 1, wn = wid & 1;       // 4 M-rows x 2 N-cols
    const int n = blockIdx.y, h = n & 15;
    const int i0 = blockIdx.x << 6;

    // stage Qu = q*0.125 + u_bias (hi/lo): 64 rows
    const float* qb = q + (size_t)n * 65536 + (size_t)i0 * 64;
    #pragma unroll
    for (int it = 0; it < 4; ++it) {
        int fi = it * 256 + tid;
        int r = fi >> 4, d = (fi & 15) << 2;
        float4 f = *(const float4*)(qb + r * 64 + d);
        float4 bs = *(const float4*)(ubias + h * 64 + d);
        f.x = f.x * 0.125f + bs.x; f.y = f.y * 0.125f + bs.y;
        f.z = f.z * 0.125f + bs.z; f.w = f.w * 0.125f + bs.w;
        uint2 H, L;
        splitpair(f.x, f.y, H.x, L.x); splitpair(f.z, f.w, H.y, L.y);
        *(uint2*)(cb + QUH_O + r * 144 + d * 2) = H;
        *(uint2*)(cb + QUL_O + r * 144 + d * 2) = L;
    }

    float oC[8][4] = {};
    float ls[2] = {};
    const float* pb = g_pos + (size_t)n * (1024 * PITCH);

    const int g = lane >> 2, t4 = lane & 3;
    const int i1 = i0 + wm * 16 + g;
    const int i2 = i1 + 8;

    // cp.async: 2 chunks per thread per component (512 chunks, 256 threads)
    const int c0 = tid, c1 = tid + 256;
    const char* kbase = (const char*)g_kh + ((size_t)n << 17);
    const char* klbase = (const char*)g_kl + ((size_t)n << 17);
    const char* vbase = (const char*)g_vth + ((size_t)n << 17);
    const char* vlbase = (const char*)g_vtl + ((size_t)n << 17);
    const uint32_t so0 = (uint32_t)((c0 >> 3) * 144 + ((c0 & 7) << 4));
    const uint32_t so1 = (uint32_t)((c1 >> 3) * 144 + ((c1 & 7) << 4));
    const uint32_t ko0 = (uint32_t)((c0 >> 3) * 128 + ((c0 & 7) << 4));
    const uint32_t ko1 = (uint32_t)((c1 >> 3) * 128 + ((c1 & 7) << 4));
    const uint32_t vo0 = (uint32_t)((c0 >> 3) * 2048 + ((c0 & 7) << 4));
    const uint32_t vo1 = (uint32_t)((c1 >> 3) * 2048 + ((c1 & 7) << 4));

    #define ISSUE(kt, st) do {                                                   \
        const char* _k = kbase + ((size_t)(kt) << 13);                           \
        const char* _kl = klbase + ((size_t)(kt) << 13);                         \
        const char* _v = vbase + ((uint32_t)(kt) << 7);                          \
        const char* _vl = vlbase + ((uint32_t)(kt) << 7);                        \
        CPA16(sb + (st) + so0,         _k + ko0);                                \
        CPA16(sb + (st) + so1,         _k + ko1);                                \
        CPA16(sb + (st) + 9216 + so0,  _kl + ko0);                               \
        CPA16(sb + (st) + 9216 + so1,  _kl + ko1);                               \
        CPA16(sb + (st) + 18432 + so0, _v + vo0);                                \
        CPA16(sb + (st) + 18432 + so1, _v + vo1);                                \
        CPA16(sb + (st) + 27648 + so0, _vl + vo0);                               \
        CPA16(sb + (st) + 27648 + so1, _vl + vo1);                               \
        CPA_COMMIT();                                                            \
    } while (0)

    ISSUE(0, ST0_O);

    for (int kt = 0; kt < 16; ++kt) {
        const uint32_t st = ST0_O + (kt & 1) * ST_SZ;

        // ---- prefetch shifted pos values (independent of the pipeline) ----
        float pr[4][4];
        #pragma unroll
        for (int nt = 0; nt < 4; ++nt) {
            const int j = (kt << 6) + wn * 32 + nt * 8 + (t4 << 1);
            float2 pp = pos2(pb, i1, j);
            pr[nt][0] = pp.x; pr[nt][1] = pp.y;
            pp = pos2(pb, i2, j);
            pr[nt][2] = pp.x; pr[nt][3] = pp.y;
        }

        asm volatile("cp.async.wait_group 0;" ::: "memory");
        __syncthreads();   // buf kt fully visible; ALL warps finished iter kt-1
        if (kt < 15) ISSUE(kt + 1, ST0_O + ((kt + 1) & 1) * ST_SZ);
        // safe: readers of buf (kt+1)&1 were in iter kt-1, done before barrier

        // ---- S = Qu . K^T  (bf16x3, ldsm4-merged K loads) ----
        float sC[4][4] = {};
        #pragma unroll
        for (int ks = 0; ks < 4; ++ks) {
            uint32_t qh[4], ql[4], kh[2][4], kl[2][4];
            uint32_t qa = (wm * 16 + (lane & 15)) * 144 +
                          (ks * 16 + ((lane >> 4) << 3)) * 2;
            ldsm4(qh, sb + QUH_O + qa);
            ldsm4(ql, sb + QUL_O + qa);
            #pragma unroll
            for (int p = 0; p < 2; ++p) {
                uint32_t ao = (wn * 32 + p * 16 + (lane & 7) + ((lane >> 4) << 3)) * 144 +
                              (ks * 16 + (((lane >> 3) & 1) << 3)) * 2;
                ldsm4(kh[p], st + sb + ao);
                ldsm4(kl[p], st + sb + 9216 + ao);
            }
            #pragma unroll
            for (int p = 0; p < 2; ++p) {
                mma16816(sC[2*p],     qh, kh[p]);
                mma16816(sC[2*p],     qh, kl[p]);
                mma16816(sC[2*p],     ql, kh[p]);
                mma16816(sC[2*p + 1], qh, kh[p] + 2);
                mma16816(sC[2*p + 1], qh, kl[p] + 2);
                mma16816(sC[2*p + 1], ql, kh[p] + 2);
            }
        }

        // ---- exp(S + pos), pack into A fragments (no smem P) ----
        uint32_t aH[2][4], aL[2][4];
        #pragma unroll
        for (int nt = 0; nt < 4; ++nt) {
            float e0 = __expf(sC[nt][0] + pr[nt][0]);
            float e1 = __expf(sC[nt][1] + pr[nt][1]);
            float e2 = __expf(sC[nt][2] + pr[nt][2]);
            float e3 = __expf(sC[nt][3] + pr[nt][3]);
            ls[0] += e0 + e1;
            ls[1] += e2 + e3;
            const int kk = nt >> 1, half = (nt & 1) << 1;
            splitpair(e0, e1, aH[kk][half + 0], aL[kk][half + 0]);
            splitpair(e2, e3, aH[kk][half + 1], aL[kk][half + 1]);
        }

        // ---- O += P . V  (ldsm4-merged V loads; k-slice wn*32..+32) ----
        #pragma unroll
        for (int kk = 0; kk < 2; ++kk) {
            #pragma unroll
            for (int d2 = 0; d2 < 4; ++d2) {
                uint32_t vh[4], vl[4];
                uint32_t ao = (d2 * 16 + (lane & 7) + ((lane >> 4) << 3)) * 144 +
                              (wn * 32 + kk * 16 + (((lane >> 3) & 1) << 3)) * 2;
                ldsm4(vh, st + sb + 18432 + ao);
                ldsm4(vl, st + sb + 27648 + ao);
                mma16816(oC[2*d2],     aH[kk], vh);
                mma16816(oC[2*d2],     aH[kk], vl);
                mma16816(oC[2*d2],     aL[kk], vh);
                mma16816(oC[2*d2 + 1], aH[kk], vh + 2);
                mma16816(oC[2*d2 + 1], aH[kk], vl + 2);
                mma16816(oC[2*d2 + 1], aL[kk], vh + 2);
            }
        }
    }
    #undef ISSUE

    // ---- row-sum reduction: quad lanes, then the 2 wn warps via smem ----
    float* lsm = (float*)(cb + LS_O);
    #pragma unroll
    for (int p = 0; p < 2; ++p) {
        float vv = ls[p];
        vv += __shfl_xor_sync(0xffffffffu, vv, 1);
        vv += __shfl_xor_sync(0xffffffffu, vv, 2);
        ls[p] = vv;
    }
    if ((lane & 3) == 0) {
        lsm[wn * 64 + wm * 16 + g] = ls[0];
        lsm[wn * 64 + wm * 16 + 8 + g] = ls[1];
    }

    // ---- O partial reduction across the 2 wn warps (OB = buf0; last iter
    //      readers used buf1, and buf0's readers finished at the kt=15 barrier) ----
    float* ob = (float*)(cb + OB_O);
    if (wn == 1) {
        #pragma unroll
        for (int dn = 0; dn < 8; ++dn) {
            const int col = dn * 8 + (t4 << 1);
            *(float2*)&ob[(wm * 16 + g) * 64 + col] = make_float2(oC[dn][0], oC[dn][1]);
            *(float2*)&ob[(wm * 16 + 8 + g) * 64 + col] = make_float2(oC[dn][2], oC[dn][3]);
        }
    }
    __syncthreads();
    if (wn == 0) {
        const int r1 = wm * 16 + g, r2 = r1 + 8;
        const float inv1 = 1.0f / (lsm[r1] + lsm[64 + r1]);
        const float inv2 = 1.0f / (lsm[r2] + lsm[64 + r2]);
        float* ob1 = out + (size_t)n * 65536 + (size_t)(i0 + r1) * 64;
        float* ob2 = out + (size_t)n * 65536 + (size_t)(i0 + r2) * 64;
        #pragma unroll
        for (int dn = 0; dn < 8; ++dn) {
            const int col = dn * 8 + (t4 << 1);
            float2 p1 = *(float2*)&ob[r1 * 64 + col];
            float2 p2 = *(float2*)&ob[r2 * 64 + col];
            *(float2*)(ob1 + col) = make_float2((oC[dn][0] + p1.x) * inv1,
                                                (oC[dn][1] + p1.y) * inv1);
            *(float2*)(ob2 + col) = make_float2((oC[dn][2] + p2.x) * inv2,
                                                (oC[dn][3] + p2.y) * inv2);
        }
    }
}

// ---------------------------------------------------------------------------
extern "C" void kernel_launch(void* const* d_in, const int* in_sizes, int n_in,
                              void* d_out, int out_size)
{
    const float* q  = (const float*)d_in[0];
    const float* k  = (const float*)d_in[1];
    const float* v  = (const float*)d_in[2];
    const float* ub = (const float*)d_in[3];
    const float* vb = (const float*)d_in[4];
    const float* R  = (const float*)d_in[5];
    float* out = (float*)d_out;

    cudaFuncSetAttribute(pos_mma, cudaFuncAttributeMaxDynamicSharedMemorySize, POS_SMEM);
    cudaFuncSetAttribute(flash_mma, cudaFuncAttributeMaxDynamicSharedMemorySize, FLASH_SMEM);

    prep_kv<<<dim3(16, 64), 256>>>(k, v);
    prep_r<<<dim3(16, 16), 256>>>(R);
    pos_mma<<<dim3(16, 64), 256, POS_SMEM>>>(q, vb);
    flash_mma<<<dim3(16, 64), 256, FLASH_SMEM>>>(q, ub, out);
}